// round 1
// baseline (speedup 1.0000x reference)
#include <cuda_runtime.h>
#include <cstdint>
#include <math.h>

#define EMBED   256
#define HIDDEN  512
#define NB      64
#define LSTEPS  2048

// xp[t][n][h] scratch: 2048*64*512 floats = 256MB (static device array, no alloc)
__device__ float g_xp[(size_t)LSTEPS * NB * HIDDEN];

// ============================================================================
// Phase 1: xp[l][n][j] = b_xh[j] + sum_d E[X[n][l]][d] * W_xh[d][j]
// Classic 128x128x16 fp32 tiled GEMM, 8x8 register blocking, gather A rows.
// ============================================================================
#define BM 128
#define BN 128
#define BK 16

__global__ void __launch_bounds__(256)
proj_kernel(const int* __restrict__ X, const float* __restrict__ E,
            const float* __restrict__ Wxh, const float* __restrict__ bxh)
{
    __shared__ float As[BK][BM];   // [k][m]
    __shared__ float Bs[BK][BN];   // [k][j]
    __shared__ int   toks[BM];

    const int tid   = threadIdx.x;
    const int mtile = blockIdx.y;          // 0..1023
    const int n     = mtile >> 4;          // 2048/128 = 16 m-tiles per batch row
    const int l0    = (mtile & 15) * BM;
    const int j0    = blockIdx.x * BN;     // 0..3

    if (tid < BM) toks[tid] = X[n * LSTEPS + l0 + tid];
    __syncthreads();

    const int ty = tid >> 4;
    const int tx = tid & 15;

    float acc[8][8];
#pragma unroll
    for (int i = 0; i < 8; i++)
#pragma unroll
        for (int j = 0; j < 8; j++) acc[i][j] = 0.f;

    for (int k0 = 0; k0 < EMBED; k0 += BK) {
        // A: gather 128 embedding rows, 16 k's (512 float4 total)
#pragma unroll
        for (int u = 0; u < 2; u++) {
            int f  = tid + u * 256;
            int m  = f & 127;
            int kq = f >> 7;   // 0..3
            float4 v = *(const float4*)&E[(size_t)toks[m] * EMBED + k0 + kq * 4];
            As[kq * 4 + 0][m] = v.x;
            As[kq * 4 + 1][m] = v.y;
            As[kq * 4 + 2][m] = v.z;
            As[kq * 4 + 3][m] = v.w;
        }
        // B: W_xh tile (coalesced)
#pragma unroll
        for (int u = 0; u < 2; u++) {
            int f  = tid + u * 256;
            int kk = f >> 5;          // 0..15
            int jj = (f & 31) * 4;    // 0..124
            *(float4*)&Bs[kk][jj] =
                *(const float4*)&Wxh[(size_t)(k0 + kk) * HIDDEN + j0 + jj];
        }
        __syncthreads();
#pragma unroll
        for (int kk = 0; kk < BK; kk++) {
            float a[8], b[8];
            *(float4*)&a[0] = *(const float4*)&As[kk][ty * 8];
            *(float4*)&a[4] = *(const float4*)&As[kk][ty * 8 + 4];
            *(float4*)&b[0] = *(const float4*)&Bs[kk][tx * 8];
            *(float4*)&b[4] = *(const float4*)&Bs[kk][tx * 8 + 4];
#pragma unroll
            for (int i = 0; i < 8; i++)
#pragma unroll
                for (int j = 0; j < 8; j++)
                    acc[i][j] += a[i] * b[j];
        }
        __syncthreads();
    }

    float bx[8];
#pragma unroll
    for (int q = 0; q < 8; q++) bx[q] = bxh[j0 + tx * 8 + q];

#pragma unroll
    for (int i = 0; i < 8; i++) {
        int l = l0 + ty * 8 + i;
        float* dst = g_xp + (size_t)l * (NB * HIDDEN) + n * HIDDEN + j0 + tx * 8;
        float4 v0, v1;
        v0.x = acc[i][0] + bx[0]; v0.y = acc[i][1] + bx[1];
        v0.z = acc[i][2] + bx[2]; v0.w = acc[i][3] + bx[3];
        v1.x = acc[i][4] + bx[4]; v1.y = acc[i][5] + bx[5];
        v1.z = acc[i][6] + bx[6]; v1.w = acc[i][7] + bx[7];
        *(float4*)dst       = v0;
        *(float4*)(dst + 4) = v1;
    }
}

// ============================================================================
// Phase 2: persistent cluster RNN.
// 16 clusters x 8 CTAs (128 SMs). Cluster g owns batch rows 4g..4g+3.
// Rank r holds W_hh[:, 64r:64r+64] fp32 in smem (transposed+padded).
// Per step: each CTA computes its (4 x 64) slice, tanh, DSMEM-pushes the
// slice into all 8 peers' double-buffered h; one cluster barrier per step.
// ============================================================================
#define CL   8
#define RB   4
#define JSL  64
#define WSTR 516   // 516 % 32 == 4 -> conflict-free LDS.128 across consecutive j

struct Smem2 {
    float Wt[JSL * WSTR];        // Wt[j][k] = W_hh[k][j0+j]     (132096 B)
    float hbuf[2][RB * HIDDEN];  // double-buffered full h       (16384 B)
    float red[4 * RB * JSL];     // k-group partials             (4096 B)
    float stage[RB * JSL];       // h_new slice staging          (1024 B)
    float bh[JSL];               // b_hh slice                   (256 B)
};
#define SMEM2_BYTES ((int)sizeof(Smem2))

__device__ __forceinline__ uint32_t smem_u32(const void* p) {
    uint32_t a;
    asm("{ .reg .u64 t; cvta.to.shared.u64 t, %1; cvt.u32.u64 %0, t; }"
        : "=r"(a) : "l"(p));
    return a;
}
__device__ __forceinline__ uint32_t mapa_u32(uint32_t a, uint32_t rank) {
    uint32_t r;
    asm("mapa.shared::cluster.u32 %0, %1, %2;" : "=r"(r) : "r"(a), "r"(rank));
    return r;
}
__device__ __forceinline__ void stc_f32x4(uint32_t a, float4 v) {
    asm volatile("st.shared::cluster.v4.f32 [%0], {%1,%2,%3,%4};"
                 :: "r"(a), "f"(v.x), "f"(v.y), "f"(v.z), "f"(v.w) : "memory");
}
__device__ __forceinline__ void cluster_arrive() {
    asm volatile("barrier.cluster.arrive.aligned;" ::: "memory");
}
__device__ __forceinline__ void cluster_wait() {
    asm volatile("barrier.cluster.wait.aligned;" ::: "memory");
}

extern __shared__ float smem2_raw[];

__global__ void __cluster_dims__(CL, 1, 1) __launch_bounds__(256, 1)
rnn_kernel(const float* __restrict__ Whh, const float* __restrict__ bhh,
           float* __restrict__ out)
{
    Smem2* s = (Smem2*)smem2_raw;
    const int tid  = threadIdx.x;
    const int rank = blockIdx.x;     // 0..7  (== cluster ctarank)
    const int g    = blockIdx.y;     // 0..15
    const int j0   = rank * JSL;
    const int n0   = g * RB;

    // ---- init: W slice (transposed, padded), bias, zero h buffers ----
    for (int idx = tid; idx < HIDDEN * JSL; idx += 256) {
        int k = idx >> 6;        // 0..511
        int j = idx & 63;
        s->Wt[j * WSTR + k] = Whh[(size_t)k * HIDDEN + j0 + j];
    }
    if (tid < JSL) s->bh[tid] = bhh[j0 + tid];
    for (int idx = tid; idx < 2 * RB * HIDDEN; idx += 256)
        ((float*)s->hbuf)[idx] = 0.f;
    __syncthreads();
    cluster_arrive();

    const int jq = tid & 63;   // output column within slice (both roles)
    const int kg = tid >> 6;   // compute role: k-group 0..3 (128 k each)
    const int ir = tid >> 6;   // reduce role: batch row 0..3

    // precompute per-rank DSMEM base addresses of hbuf
    uint32_t hb_u32 = smem_u32(&s->hbuf[0][0]);
    uint32_t peer_base[CL];
#pragma unroll
    for (int r = 0; r < CL; r++) peer_base[r] = mapa_u32(hb_u32, (uint32_t)r);

    const float* Wrow = &s->Wt[jq * WSTR + kg * 128];
    const size_t xoff = (size_t)NB * HIDDEN;                 // 32768
    const float* xp_ptr = g_xp + (size_t)(n0 + ir) * HIDDEN + j0 + jq;

    cluster_wait();   // all CTAs initialized (peers may be pushed into)

    float xp_reg = __ldcs(xp_ptr);          // step 0 value
    const float* xnp = xp_ptr + xoff;
    int cur = 0;

    for (int t = 0; t < LSTEPS; t++) {
        float xp_nx = (t + 1 < LSTEPS) ? __ldcs(xnp) : 0.f;  // prefetch t+1

        const float* hb = &s->hbuf[cur][kg * 128];
        float a0 = 0.f, a1 = 0.f, a2 = 0.f, a3 = 0.f;
#pragma unroll 8
        for (int kk = 0; kk < 128; kk += 4) {
            float4 w  = *(const float4*)(Wrow + kk);
            float4 p0 = *(const float4*)(hb + kk);
            float4 p1 = *(const float4*)(hb + HIDDEN + kk);
            float4 p2 = *(const float4*)(hb + 2 * HIDDEN + kk);
            float4 p3 = *(const float4*)(hb + 3 * HIDDEN + kk);
            a0 += w.x * p0.x; a0 += w.y * p0.y; a0 += w.z * p0.z; a0 += w.w * p0.w;
            a1 += w.x * p1.x; a1 += w.y * p1.y; a1 += w.z * p1.z; a1 += w.w * p1.w;
            a2 += w.x * p2.x; a2 += w.y * p2.y; a2 += w.z * p2.z; a2 += w.w * p2.w;
            a3 += w.x * p3.x; a3 += w.y * p3.y; a3 += w.z * p3.z; a3 += w.w * p3.w;
        }
        s->red[(kg * RB + 0) * JSL + jq] = a0;
        s->red[(kg * RB + 1) * JSL + jq] = a1;
        s->red[(kg * RB + 2) * JSL + jq] = a2;
        s->red[(kg * RB + 3) * JSL + jq] = a3;
        __syncthreads();

        float sum = s->red[(0 * RB + ir) * JSL + jq]
                  + s->red[(1 * RB + ir) * JSL + jq]
                  + s->red[(2 * RB + ir) * JSL + jq]
                  + s->red[(3 * RB + ir) * JSL + jq]
                  + s->bh[jq] + xp_reg;
        float hn = tanhf(sum);

        if (t == LSTEPS - 1) {
            out[(n0 + ir) * HIDDEN + j0 + jq] = hn;
        } else {
            s->stage[ir * JSL + jq] = hn;
            __syncthreads();
            int nxt = cur ^ 1;
            if (tid < 64) {
                int i2 = tid >> 4;
                int jj = (tid & 15) * 4;
                float4 v = *(const float4*)&s->stage[i2 * JSL + jj];
                uint32_t off =
                    (uint32_t)((nxt * (RB * HIDDEN) + i2 * HIDDEN + j0 + jj) * 4);
#pragma unroll
                for (int r = 0; r < CL; r++)
                    stc_f32x4(peer_base[r] + off, v);
            }
            cluster_arrive();          // release: pushes visible after wait
            xp_reg = xp_nx;            // overlap sync latency
            xnp += xoff;
            cluster_wait();
        }
        cur ^= 1;
    }
}

// ============================================================================
extern "C" void kernel_launch(void* const* d_in, const int* in_sizes, int n_in,
                              void* d_out, int out_size)
{
    const int*   X   = (const int*)d_in[0];
    const float* E   = (const float*)d_in[1];
    const float* Whh = (const float*)d_in[2];
    const float* bhh = (const float*)d_in[3];
    const float* Wxh = (const float*)d_in[4];
    const float* bxh = (const float*)d_in[5];
    float* out = (float*)d_out;

    cudaFuncSetAttribute(rnn_kernel,
                         cudaFuncAttributeMaxDynamicSharedMemorySize,
                         SMEM2_BYTES);

    proj_kernel<<<dim3(4, 1024), 256>>>(X, E, Wxh, bxh);
    rnn_kernel<<<dim3(CL, NB / RB), 256, SMEM2_BYTES>>>(Whh, bhh, out);
}

// round 2
// speedup vs baseline: 1.3858x; 1.3858x over previous
#include <cuda_runtime.h>
#include <cstdint>
#include <math.h>

#define EMBED   256
#define HIDDEN  512
#define NB      64
#define LSTEPS  2048

// xp[t][n][h] scratch: 2048*64*512 floats = 256MB
__device__ float g_xp[(size_t)LSTEPS * NB * HIDDEN];

// ---- packed f32x2 helpers (Blackwell) ----
#define FMA_F32X2(acc, a, b) \
    asm("fma.rn.f32x2 %0, %1, %2, %0;" : "+l"(acc) : "l"(a), "l"(b))
#define PACK_F32X2(out, lo, hi) \
    asm("mov.b64 %0, {%1, %2};" : "=l"(out) : "f"(lo), "f"(hi))
#define UNPACK_F32X2(lo, hi, in) \
    asm("mov.b64 {%0, %1}, %2;" : "=f"(lo), "=f"(hi) : "l"(in))

// ============================================================================
// Phase 1: xp[l][n][j] = b_xh[j] + sum_d E[X[n][l]][d] * W_xh[d][j]
// 128x128x16 tiled GEMM, 8x8 register tile, FFMA2 inner product.
// ============================================================================
#define BM 128
#define BN 128
#define BK 16

__global__ void __launch_bounds__(256)
proj_kernel(const int* __restrict__ X, const float* __restrict__ E,
            const float* __restrict__ Wxh, const float* __restrict__ bxh)
{
    __shared__ float As[BK][BM];
    __shared__ float Bs[BK][BN];
    __shared__ int   toks[BM];

    const int tid   = threadIdx.x;
    const int mtile = blockIdx.y;
    const int n     = mtile >> 4;
    const int l0    = (mtile & 15) * BM;
    const int j0    = blockIdx.x * BN;

    if (tid < BM) toks[tid] = X[n * LSTEPS + l0 + tid];
    __syncthreads();

    const int ty = tid >> 4;
    const int tx = tid & 15;

    unsigned long long acc[8][4];   // 8 i-rows x 4 j-pairs
#pragma unroll
    for (int i = 0; i < 8; i++)
#pragma unroll
        for (int j = 0; j < 4; j++) acc[i][j] = 0ULL;

    for (int k0 = 0; k0 < EMBED; k0 += BK) {
#pragma unroll
        for (int u = 0; u < 2; u++) {
            int f  = tid + u * 256;
            int m  = f & 127;
            int kq = f >> 7;
            float4 v = *(const float4*)&E[(size_t)toks[m] * EMBED + k0 + kq * 4];
            As[kq * 4 + 0][m] = v.x;
            As[kq * 4 + 1][m] = v.y;
            As[kq * 4 + 2][m] = v.z;
            As[kq * 4 + 3][m] = v.w;
        }
#pragma unroll
        for (int u = 0; u < 2; u++) {
            int f  = tid + u * 256;
            int kk = f >> 5;
            int jj = (f & 31) * 4;
            *(float4*)&Bs[kk][jj] =
                *(const float4*)&Wxh[(size_t)(k0 + kk) * HIDDEN + j0 + jj];
        }
        __syncthreads();
#pragma unroll
        for (int kk = 0; kk < BK; kk++) {
            float a[8];
            *(float4*)&a[0] = *(const float4*)&As[kk][ty * 8];
            *(float4*)&a[4] = *(const float4*)&As[kk][ty * 8 + 4];
            ulonglong2 b01 = *(const ulonglong2*)&Bs[kk][tx * 8];
            ulonglong2 b23 = *(const ulonglong2*)&Bs[kk][tx * 8 + 4];
            unsigned long long bp[4] = {b01.x, b01.y, b23.x, b23.y};
#pragma unroll
            for (int i = 0; i < 8; i++) {
                unsigned long long aa;
                PACK_F32X2(aa, a[i], a[i]);
#pragma unroll
                for (int j = 0; j < 4; j++)
                    FMA_F32X2(acc[i][j], aa, bp[j]);
            }
        }
        __syncthreads();
    }

    float bx[8];
#pragma unroll
    for (int q = 0; q < 8; q++) bx[q] = bxh[j0 + tx * 8 + q];

#pragma unroll
    for (int i = 0; i < 8; i++) {
        int l = l0 + ty * 8 + i;
        float* dst = g_xp + (size_t)l * (NB * HIDDEN) + n * HIDDEN + j0 + tx * 8;
        float r[8];
#pragma unroll
        for (int j = 0; j < 4; j++) {
            float lo, hi;
            UNPACK_F32X2(lo, hi, acc[i][j]);
            r[j * 2]     = lo + bx[j * 2];
            r[j * 2 + 1] = hi + bx[j * 2 + 1];
        }
        *(float4*)dst       = make_float4(r[0], r[1], r[2], r[3]);
        *(float4*)(dst + 4) = make_float4(r[4], r[5], r[6], r[7]);
    }
}

// ============================================================================
// Phase 2: persistent cluster RNN. 16 clusters x 8 CTAs.
// Rank r owns output slice j in [64r, 64r+64), 4 batch rows per cluster.
// W_hh slice lives in REGISTERS: thread (kg=warp, jg=lane) holds
// W[k in kg*64..+64)][j0 + jg*2 + {0,1}] = 64 packed f32x2 regs.
// Per step: FFMA2 inner product -> 8-way smem reduce -> tanh -> shfl-gather
// float4 -> DSMEM push to 8 peers -> mbarrier arrive/wait (no barrier.cluster).
// ============================================================================
#define CL   8
#define RB   4
#define JSL  64

struct Smem2 {
    float hbuf[2][RB * HIDDEN];              // 16 KB double-buffered h
    float red[8][RB][JSL];                   // 8 KB  per-warp partials
    float bh[JSL];
    unsigned long long mbar;                 // cluster-sync mbarrier
};

__device__ __forceinline__ uint32_t smem_u32(const void* p) {
    uint32_t a;
    asm("{ .reg .u64 t; cvta.to.shared.u64 t, %1; cvt.u32.u64 %0, t; }"
        : "=r"(a) : "l"(p));
    return a;
}
__device__ __forceinline__ uint32_t mapa_u32(uint32_t a, uint32_t rank) {
    uint32_t r;
    asm("mapa.shared::cluster.u32 %0, %1, %2;" : "=r"(r) : "r"(a), "r"(rank));
    return r;
}
__device__ __forceinline__ void stc_f32x4(uint32_t a, float4 v) {
    asm volatile("st.shared::cluster.v4.f32 [%0], {%1,%2,%3,%4};"
                 :: "r"(a), "f"(v.x), "f"(v.y), "f"(v.z), "f"(v.w) : "memory");
}
__device__ __forceinline__ void mbar_init(uint32_t a, uint32_t cnt) {
    asm volatile("mbarrier.init.shared.b64 [%0], %1;" :: "r"(a), "r"(cnt) : "memory");
}
__device__ __forceinline__ void mbar_arrive_remote(uint32_t a) {
    asm volatile("mbarrier.arrive.release.cluster.shared::cluster.b64 _, [%0];"
                 :: "r"(a) : "memory");
}
__device__ __forceinline__ void mbar_wait_parity(uint32_t a, uint32_t parity) {
    asm volatile(
        "{\n\t.reg .pred P;\n\t"
        "WL_%=:\n\t"
        "mbarrier.try_wait.parity.acquire.cluster.shared::cta.b64 P, [%0], %1, 0x989680;\n\t"
        "@!P bra WL_%=;\n\t}"
        :: "r"(a), "r"(parity) : "memory");
}
__device__ __forceinline__ void cluster_sync_() {
    asm volatile("barrier.cluster.arrive.aligned;" ::: "memory");
    asm volatile("barrier.cluster.wait.aligned;" ::: "memory");
}

__global__ void __cluster_dims__(CL, 1, 1) __launch_bounds__(256, 1)
rnn_kernel(const float* __restrict__ Whh, const float* __restrict__ bhh,
           float* __restrict__ out)
{
    __shared__ Smem2 s;
    const int tid  = threadIdx.x;
    const int rank = blockIdx.x;      // 0..7
    const int g    = blockIdx.y;      // 0..15
    const int j0   = rank * JSL;
    const int n0   = g * RB;

    const int kg = tid >> 5;          // warp id = k-group (64 k each)
    const int jg = tid & 31;          // lane -> j pair (j0 + jg*2, +1)

    // ---- load W slice into registers: 64 packed f32x2 ----
    // Wr[i*4 + j*2 + p] = (Whh[kb+i*4+2p][jcol+j], Whh[kb+i*4+2p+1][jcol+j])
    unsigned long long Wr[64];
    {
        const int kb   = kg * 64;
        const int jcol = j0 + jg * 2;
#pragma unroll
        for (int i = 0; i < 16; i++) {
#pragma unroll
            for (int p = 0; p < 2; p++) {
                int k = kb + i * 4 + p * 2;
                float2 w0 = *(const float2*)&Whh[(size_t)k * HIDDEN + jcol];
                float2 w1 = *(const float2*)&Whh[(size_t)(k + 1) * HIDDEN + jcol];
                PACK_F32X2(Wr[i * 4 + 0 * 2 + p], w0.x, w1.x);
                PACK_F32X2(Wr[i * 4 + 1 * 2 + p], w0.y, w1.y);
            }
        }
    }

    // ---- init smem ----
    for (int idx = tid; idx < 2 * RB * HIDDEN; idx += 256)
        ((float*)s.hbuf)[idx] = 0.f;
    if (tid < JSL) s.bh[tid] = bhh[j0 + tid];
    const uint32_t mbar_a = smem_u32(&s.mbar);
    if (tid == 0) {
        mbar_init(mbar_a, CL);   // 8 arrivals per phase (one per CTA)
        asm volatile("fence.mbarrier_init.release.cluster;" ::: "memory");
    }
    __syncthreads();
    cluster_sync_();   // all CTAs: smem zeroed + mbarriers visible

    // reduce-role mapping
    const int rrow = tid >> 6;        // 0..3
    const int rj   = tid & 63;        // 0..63
    const int lane = tid & 31;
    const int l0v  = lane & ~3;       // float4 group leader lane
    const int jb   = rj & ~3;         // j base of this lane's float4 group

    const uint32_t hb_u32 = smem_u32(&s.hbuf[0][0]);
    const size_t xstride = (size_t)NB * HIDDEN;
    const float* xp_ptr = g_xp + (size_t)(n0 + rrow) * HIDDEN + j0 + rj;

    float xp_reg = __ldcs(xp_ptr);
    const float* xnp = xp_ptr + xstride;

    for (int t = 0; t < LSTEPS; t++) {
        const int cur = t & 1;
        const int nxt = cur ^ 1;
        float xp_nx = (t + 1 < LSTEPS) ? __ldcs(xnp) : 0.f;

        // ---- inner product: acc[r*2+j] over 64 k (packed pairs) ----
        const ulonglong2* hbv =
            (const ulonglong2*)&s.hbuf[cur][kg * 64];   // +128 per row (ull2)
        unsigned long long acc[8];
#pragma unroll
        for (int q = 0; q < 8; q++) acc[q] = 0ULL;

#pragma unroll
        for (int i = 0; i < 16; i++) {
            ulonglong2 h0 = hbv[i];
            ulonglong2 h1 = hbv[128 + i];
            ulonglong2 h2 = hbv[256 + i];
            ulonglong2 h3 = hbv[384 + i];
            FMA_F32X2(acc[0], Wr[i * 4 + 0], h0.x);
            FMA_F32X2(acc[0], Wr[i * 4 + 1], h0.y);
            FMA_F32X2(acc[1], Wr[i * 4 + 2], h0.x);
            FMA_F32X2(acc[1], Wr[i * 4 + 3], h0.y);
            FMA_F32X2(acc[2], Wr[i * 4 + 0], h1.x);
            FMA_F32X2(acc[2], Wr[i * 4 + 1], h1.y);
            FMA_F32X2(acc[3], Wr[i * 4 + 2], h1.x);
            FMA_F32X2(acc[3], Wr[i * 4 + 3], h1.y);
            FMA_F32X2(acc[4], Wr[i * 4 + 0], h2.x);
            FMA_F32X2(acc[4], Wr[i * 4 + 1], h2.y);
            FMA_F32X2(acc[5], Wr[i * 4 + 2], h2.x);
            FMA_F32X2(acc[5], Wr[i * 4 + 3], h2.y);
            FMA_F32X2(acc[6], Wr[i * 4 + 0], h3.x);
            FMA_F32X2(acc[6], Wr[i * 4 + 1], h3.y);
            FMA_F32X2(acc[7], Wr[i * 4 + 2], h3.x);
            FMA_F32X2(acc[7], Wr[i * 4 + 3], h3.y);
        }

        // partials -> red[kg][r][jg*2 + {0,1}]
#pragma unroll
        for (int r = 0; r < RB; r++) {
            float lo0, hi0, lo1, hi1;
            UNPACK_F32X2(lo0, hi0, acc[r * 2 + 0]);
            UNPACK_F32X2(lo1, hi1, acc[r * 2 + 1]);
            *(float2*)&s.red[kg][r][jg * 2] = make_float2(lo0 + hi0, lo1 + hi1);
        }
        __syncthreads();

        // ---- 8-way reduce + tanh ----
        float sum = s.bh[rj] + xp_reg;
#pragma unroll
        for (int w = 0; w < 8; w++) sum += s.red[w][rrow][rj];
        float hn = tanhf(sum);

        if (t == LSTEPS - 1) {
            out[(n0 + rrow) * HIDDEN + j0 + rj] = hn;
        } else {
            // shfl-gather float4 within groups of 4 lanes (consecutive j)
            float v0 = __shfl_sync(0xffffffffu, hn, l0v);
            float v1 = __shfl_sync(0xffffffffu, hn, l0v + 1);
            float v2 = __shfl_sync(0xffffffffu, hn, l0v + 2);
            float v3 = __shfl_sync(0xffffffffu, hn, l0v + 3);
            if ((lane & 3) == 0) {
                float4 v = make_float4(v0, v1, v2, v3);
                uint32_t off = (uint32_t)((nxt * (RB * HIDDEN)
                                           + rrow * HIDDEN + j0 + jb) * 4);
                uint32_t local = hb_u32 + off;
#pragma unroll
                for (int r = 0; r < CL; r++)
                    stc_f32x4(mapa_u32(local, (uint32_t)r), v);
            }
            __syncthreads();                 // all pushes program-ordered
            if (tid < CL)
                mbar_arrive_remote(mapa_u32(mbar_a, (uint32_t)tid));
            xp_reg = xp_nx;
            xnp += xstride;
            mbar_wait_parity(mbar_a, (uint32_t)(t & 1));
        }
    }
}

// ============================================================================
extern "C" void kernel_launch(void* const* d_in, const int* in_sizes, int n_in,
                              void* d_out, int out_size)
{
    const int*   X   = (const int*)d_in[0];
    const float* E   = (const float*)d_in[1];
    const float* Whh = (const float*)d_in[2];
    const float* bhh = (const float*)d_in[3];
    const float* Wxh = (const float*)d_in[4];
    const float* bxh = (const float*)d_in[5];
    float* out = (float*)d_out;

    proj_kernel<<<dim3(4, 1024), 256>>>(X, E, Wxh, bxh);
    rnn_kernel<<<dim3(CL, NB / RB), 256>>>(Whh, bhh, out);
}

// round 5
// speedup vs baseline: 1.7581x; 1.2687x over previous
#include <cuda_runtime.h>
#include <cstdint>
#include <math.h>

#define EMBED   256
#define HIDDEN  512
#define NB      64
#define LSTEPS  2048

// xp[t][n][h] scratch: 2048*64*512 floats = 256MB
__device__ float g_xp[(size_t)LSTEPS * NB * HIDDEN];

// ---- packed f32x2 helpers (Blackwell) ----
#define FMA_F32X2(acc, a, b) \
    asm("fma.rn.f32x2 %0, %1, %2, %0;" : "+l"(acc) : "l"(a), "l"(b))
#define PACK_F32X2(out, lo, hi) \
    asm("mov.b64 %0, {%1, %2};" : "=l"(out) : "f"(lo), "f"(hi))
#define UNPACK_F32X2(lo, hi, in) \
    asm("mov.b64 {%0, %1}, %2;" : "=f"(lo), "=f"(hi) : "l"(in))

// ============================================================================
// Phase 1: xp[l][n][j] = b_xh[j] + sum_d E[X[n][l]][d] * W_xh[d][j]
// ============================================================================
#define BM 128
#define BN 128
#define BK 16

__global__ void __launch_bounds__(256)
proj_kernel(const int* __restrict__ X, const float* __restrict__ E,
            const float* __restrict__ Wxh, const float* __restrict__ bxh)
{
    __shared__ float As[BK][BM];
    __shared__ float Bs[BK][BN];
    __shared__ int   toks[BM];

    const int tid   = threadIdx.x;
    const int mtile = blockIdx.y;
    const int n     = mtile >> 4;
    const int l0    = (mtile & 15) * BM;
    const int j0    = blockIdx.x * BN;

    if (tid < BM) toks[tid] = X[n * LSTEPS + l0 + tid];
    __syncthreads();

    const int ty = tid >> 4;
    const int tx = tid & 15;

    unsigned long long acc[8][4];
#pragma unroll
    for (int i = 0; i < 8; i++)
#pragma unroll
        for (int j = 0; j < 4; j++) acc[i][j] = 0ULL;

    for (int k0 = 0; k0 < EMBED; k0 += BK) {
#pragma unroll
        for (int u = 0; u < 2; u++) {
            int f  = tid + u * 256;
            int m  = f & 127;
            int kq = f >> 7;
            float4 v = *(const float4*)&E[(size_t)toks[m] * EMBED + k0 + kq * 4];
            As[kq * 4 + 0][m] = v.x;
            As[kq * 4 + 1][m] = v.y;
            As[kq * 4 + 2][m] = v.z;
            As[kq * 4 + 3][m] = v.w;
        }
#pragma unroll
        for (int u = 0; u < 2; u++) {
            int f  = tid + u * 256;
            int kk = f >> 5;
            int jj = (f & 31) * 4;
            *(float4*)&Bs[kk][jj] =
                *(const float4*)&Wxh[(size_t)(k0 + kk) * HIDDEN + j0 + jj];
        }
        __syncthreads();
#pragma unroll
        for (int kk = 0; kk < BK; kk++) {
            float a[8];
            *(float4*)&a[0] = *(const float4*)&As[kk][ty * 8];
            *(float4*)&a[4] = *(const float4*)&As[kk][ty * 8 + 4];
            ulonglong2 b01 = *(const ulonglong2*)&Bs[kk][tx * 8];
            ulonglong2 b23 = *(const ulonglong2*)&Bs[kk][tx * 8 + 4];
            unsigned long long bp[4] = {b01.x, b01.y, b23.x, b23.y};
#pragma unroll
            for (int i = 0; i < 8; i++) {
                unsigned long long aa;
                PACK_F32X2(aa, a[i], a[i]);
#pragma unroll
                for (int j = 0; j < 4; j++)
                    FMA_F32X2(acc[i][j], aa, bp[j]);
            }
        }
        __syncthreads();
    }

    float bx[8];
#pragma unroll
    for (int q = 0; q < 8; q++) bx[q] = bxh[j0 + tx * 8 + q];

#pragma unroll
    for (int i = 0; i < 8; i++) {
        int l = l0 + ty * 8 + i;
        float* dst = g_xp + (size_t)l * (NB * HIDDEN) + n * HIDDEN + j0 + tx * 8;
        float r[8];
#pragma unroll
        for (int j = 0; j < 4; j++) {
            float lo, hi;
            UNPACK_F32X2(lo, hi, acc[i][j]);
            r[j * 2]     = lo + bx[j * 2];
            r[j * 2 + 1] = hi + bx[j * 2 + 1];
        }
        *(float4*)dst       = make_float4(r[0], r[1], r[2], r[3]);
        *(float4*)(dst + 4) = make_float4(r[4], r[5], r[6], r[7]);
    }
}

// ============================================================================
// Phase 2: persistent cluster RNN, 32 clusters x 4 CTAs (128 SMs).
// Cluster g owns batch rows {2g, 2g+1}. CTA rank r owns j in [128r, 128r+128).
// W slice in registers: thread (kg = tid>>6 over 128 k's, jp = tid&63 over a
// j-pair) holds 128 packed f32x2. Monolithic per-step sync (R2-proven):
// red -> sync -> reduce+tanh -> push to 4 peers -> sync -> arrive x4 -> wait.
// ============================================================================
#define CL   4
#define RB   2
#define JSL  128
#define RBH  (RB * HIDDEN)    // 1024 floats

struct Smem2 {
    float hbuf[2][RBH];              // 8 KB double-buffered h (full vector)
    float red[4][RB][JSL];           // 4 KB  per-kg partials
    float bh[JSL];                   // 512 B
    unsigned long long mbar;         // cluster-sync mbarrier
};

__device__ __forceinline__ uint32_t smem_u32(const void* p) {
    uint32_t a;
    asm("{ .reg .u64 t; cvta.to.shared.u64 t, %1; cvt.u32.u64 %0, t; }"
        : "=r"(a) : "l"(p));
    return a;
}
__device__ __forceinline__ uint32_t mapa_u32(uint32_t a, uint32_t rank) {
    uint32_t r;
    asm("mapa.shared::cluster.u32 %0, %1, %2;" : "=r"(r) : "r"(a), "r"(rank));
    return r;
}
__device__ __forceinline__ void stc_b32(uint32_t a, float v) {
    asm volatile("st.shared::cluster.b32 [%0], %1;"
                 :: "r"(a), "r"(__float_as_uint(v)) : "memory");
}
__device__ __forceinline__ void mbar_init(uint32_t a, uint32_t cnt) {
    asm volatile("mbarrier.init.shared.b64 [%0], %1;" :: "r"(a), "r"(cnt) : "memory");
}
__device__ __forceinline__ void mbar_arrive_remote(uint32_t a) {
    asm volatile("mbarrier.arrive.release.cluster.shared::cluster.b64 _, [%0];"
                 :: "r"(a) : "memory");
}
__device__ __forceinline__ void mbar_wait_parity(uint32_t a, uint32_t parity) {
    asm volatile(
        "{\n\t.reg .pred P;\n\t"
        "WL_%=:\n\t"
        "mbarrier.try_wait.parity.acquire.cluster.shared::cta.b64 P, [%0], %1, 0x989680;\n\t"
        "@!P bra WL_%=;\n\t}"
        :: "r"(a), "r"(parity) : "memory");
}
__device__ __forceinline__ void cluster_sync_() {
    asm volatile("barrier.cluster.arrive.aligned;" ::: "memory");
    asm volatile("barrier.cluster.wait.aligned;" ::: "memory");
}

// tanh = (e-1)/(e+1), e = 2^(2x*log2e); ~1e-6 abs err, branch-free.
__device__ __forceinline__ float fast_tanh(float x) {
    x = fminf(fmaxf(x, -15.0f), 15.0f);
    float e;
    asm("ex2.approx.f32 %0, %1;" : "=f"(e) : "f"(x * 2.8853900817779268f));
    float r;
    asm("rcp.approx.f32 %0, %1;" : "=f"(r) : "f"(e + 1.0f));
    return (e - 1.0f) * r;
}

__global__ void __cluster_dims__(CL, 1, 1) __launch_bounds__(256, 1)
rnn_kernel(const float* __restrict__ Whh, const float* __restrict__ bhh,
           float* __restrict__ out)
{
    __shared__ Smem2 s;
    const int tid  = threadIdx.x;
    const int rank = blockIdx.x;      // 0..3
    const int g    = blockIdx.y;      // 0..31
    const int j0   = rank * JSL;
    const int n0   = g * RB;

    const int kg = tid >> 6;          // 0..3 : k in [128kg, 128kg+128)
    const int jp = tid & 63;          // j-pair: jcol = j0 + jp*2

    // ---- W slice in registers: 128 packed f32x2 ----
    // Wr[c][i] = (Whh[kb+2i][jcol+c], Whh[kb+2i+1][jcol+c]),  i=0..63, c=0..1
    unsigned long long Wr0[64], Wr1[64];
    {
        const int kb   = kg * 128;
        const int jcol = j0 + jp * 2;
#pragma unroll
        for (int i = 0; i < 64; i++) {
            int k = kb + i * 2;
            float2 w0 = *(const float2*)&Whh[(size_t)k * HIDDEN + jcol];
            float2 w1 = *(const float2*)&Whh[(size_t)(k + 1) * HIDDEN + jcol];
            PACK_F32X2(Wr0[i], w0.x, w1.x);
            PACK_F32X2(Wr1[i], w0.y, w1.y);
        }
    }

    // ---- smem init ----
    for (int idx = tid; idx < 2 * RBH; idx += 256)
        ((float*)s.hbuf)[idx] = 0.f;
    if (tid < JSL) s.bh[tid] = bhh[j0 + tid];

    const uint32_t s_base  = smem_u32(&s);
    const uint32_t hb_off  = smem_u32(&s.hbuf[0][0]) - s_base;
    const uint32_t mb_off  = smem_u32(&s.mbar) - s_base;

    uint32_t peer_base[CL];
#pragma unroll
    for (int r = 0; r < CL; r++) peer_base[r] = mapa_u32(s_base, (uint32_t)r);

    if (tid == 0) {
        mbar_init(s_base + mb_off, CL);   // 4 arrivals per phase
        asm volatile("fence.mbarrier_init.release.cluster;" ::: "memory");
    }
    __syncthreads();
    cluster_sync_();   // mbarriers + zeroed hbuf visible cluster-wide

    // reduce/producer role
    const int rrow = tid >> 7;        // 0..1
    const int rj   = tid & 127;       // 0..127
    const uint32_t push_base = hb_off + (uint32_t)((rrow * HIDDEN + j0 + rj) * 4);

    const size_t xstride = (size_t)NB * HIDDEN;
    const float* xp_ptr = g_xp + (size_t)(n0 + rrow) * HIDDEN + j0 + rj;

    float xp_reg = __ldcs(xp_ptr);
    const float* xnp = xp_ptr + xstride;

    for (int t = 0; t < LSTEPS; t++) {
        const int cur = t & 1;
        const int nxt = cur ^ 1;
        float xp_nx = (t + 1 < LSTEPS) ? __ldcs(xnp) : 0.f;

        // ---- inner product over 128 k's, 2 rows, 1 j-pair ----
        const ulonglong2* h0v =
            (const ulonglong2*)&s.hbuf[cur][0 * HIDDEN + kg * 128];
        const ulonglong2* h1v =
            (const ulonglong2*)&s.hbuf[cur][1 * HIDDEN + kg * 128];

        unsigned long long a00 = 0ULL, a01 = 0ULL, a10 = 0ULL, a11 = 0ULL;
#pragma unroll
        for (int i = 0; i < 32; i++) {
            ulonglong2 ha = h0v[i];      // row 0: k pairs (4i,4i+1),(4i+2,4i+3)
            ulonglong2 hb = h1v[i];      // row 1
            FMA_F32X2(a00, Wr0[2 * i],     ha.x);
            FMA_F32X2(a00, Wr0[2 * i + 1], ha.y);
            FMA_F32X2(a01, Wr1[2 * i],     ha.x);
            FMA_F32X2(a01, Wr1[2 * i + 1], ha.y);
            FMA_F32X2(a10, Wr0[2 * i],     hb.x);
            FMA_F32X2(a10, Wr0[2 * i + 1], hb.y);
            FMA_F32X2(a11, Wr1[2 * i],     hb.x);
            FMA_F32X2(a11, Wr1[2 * i + 1], hb.y);
        }

        // partials -> red[kg][row][jp*2 + {0,1}]
        {
            float lo, hi, x0, x1;
            UNPACK_F32X2(lo, hi, a00); x0 = lo + hi;
            UNPACK_F32X2(lo, hi, a01); x1 = lo + hi;
            *(float2*)&s.red[kg][0][jp * 2] = make_float2(x0, x1);
            UNPACK_F32X2(lo, hi, a10); x0 = lo + hi;
            UNPACK_F32X2(lo, hi, a11); x1 = lo + hi;
            *(float2*)&s.red[kg][1][jp * 2] = make_float2(x0, x1);
        }
        __syncthreads();

        // ---- reduce + tanh ----
        float sum = s.bh[rj] + xp_reg
                  + s.red[0][rrow][rj] + s.red[1][rrow][rj]
                  + s.red[2][rrow][rj] + s.red[3][rrow][rj];
        float hn = fast_tanh(sum);

        if (t == LSTEPS - 1) {
            out[(n0 + rrow) * HIDDEN + j0 + rj] = hn;
        } else {
            // push own (row, j) element into all 4 peers' hbuf[nxt]
            const uint32_t off = push_base + (uint32_t)(nxt * RBH * 4);
#pragma unroll
            for (int r = 0; r < CL; r++)
                stc_b32(peer_base[r] + off, hn);
            __syncthreads();
            if (tid < CL)
                mbar_arrive_remote(peer_base[tid] + mb_off);
            xp_reg = xp_nx;
            xnp += xstride;
            mbar_wait_parity(s_base + mb_off, (uint32_t)(t & 1));
        }
    }
}

// ============================================================================
extern "C" void kernel_launch(void* const* d_in, const int* in_sizes, int n_in,
                              void* d_out, int out_size)
{
    const int*   X   = (const int*)d_in[0];
    const float* E   = (const float*)d_in[1];
    const float* Whh = (const float*)d_in[2];
    const float* bhh = (const float*)d_in[3];
    const float* Wxh = (const float*)d_in[4];
    const float* bxh = (const float*)d_in[5];
    float* out = (float*)d_out;

    proj_kernel<<<dim3(4, 1024), 256>>>(X, E, Wxh, bxh);
    rnn_kernel<<<dim3(CL, NB / RB), 256>>>(Whh, bhh, out);
}

// round 6
// speedup vs baseline: 2.2622x; 1.2867x over previous
#include <cuda_runtime.h>
#include <cstdint>
#include <math.h>

#define EMBED   256
#define HIDDEN  512
#define NB      64
#define LSTEPS  2048

// xp[t][n][h] scratch: 2048*64*512 floats = 256MB
__device__ float g_xp[(size_t)LSTEPS * NB * HIDDEN];

// ---- packed f32x2 helpers (Blackwell) ----
#define FMA_F32X2(acc, a, b) \
    asm("fma.rn.f32x2 %0, %1, %2, %0;" : "+l"(acc) : "l"(a), "l"(b))
#define PACK_F32X2(out, lo, hi) \
    asm("mov.b64 %0, {%1, %2};" : "=l"(out) : "f"(lo), "f"(hi))
#define UNPACK_F32X2(lo, hi, in) \
    asm("mov.b64 {%0, %1}, %2;" : "=f"(lo), "=f"(hi) : "l"(in))

// ============================================================================
// Phase 1: xp[l][n][j] = b_xh[j] + sum_d E[X[n][l]][d] * W_xh[d][j]
// (unchanged — passing, ~0.8ms)
// ============================================================================
#define BM 128
#define BN 128
#define BK 16

__global__ void __launch_bounds__(256)
proj_kernel(const int* __restrict__ X, const float* __restrict__ E,
            const float* __restrict__ Wxh, const float* __restrict__ bxh)
{
    __shared__ float As[BK][BM];
    __shared__ float Bs[BK][BN];
    __shared__ int   toks[BM];

    const int tid   = threadIdx.x;
    const int mtile = blockIdx.y;
    const int n     = mtile >> 4;
    const int l0    = (mtile & 15) * BM;
    const int j0    = blockIdx.x * BN;

    if (tid < BM) toks[tid] = X[n * LSTEPS + l0 + tid];
    __syncthreads();

    const int ty = tid >> 4;
    const int tx = tid & 15;

    unsigned long long acc[8][4];
#pragma unroll
    for (int i = 0; i < 8; i++)
#pragma unroll
        for (int j = 0; j < 4; j++) acc[i][j] = 0ULL;

    for (int k0 = 0; k0 < EMBED; k0 += BK) {
#pragma unroll
        for (int u = 0; u < 2; u++) {
            int f  = tid + u * 256;
            int m  = f & 127;
            int kq = f >> 7;
            float4 v = *(const float4*)&E[(size_t)toks[m] * EMBED + k0 + kq * 4];
            As[kq * 4 + 0][m] = v.x;
            As[kq * 4 + 1][m] = v.y;
            As[kq * 4 + 2][m] = v.z;
            As[kq * 4 + 3][m] = v.w;
        }
#pragma unroll
        for (int u = 0; u < 2; u++) {
            int f  = tid + u * 256;
            int kk = f >> 5;
            int jj = (f & 31) * 4;
            *(float4*)&Bs[kk][jj] =
                *(const float4*)&Wxh[(size_t)(k0 + kk) * HIDDEN + j0 + jj];
        }
        __syncthreads();
#pragma unroll
        for (int kk = 0; kk < BK; kk++) {
            float a[8];
            *(float4*)&a[0] = *(const float4*)&As[kk][ty * 8];
            *(float4*)&a[4] = *(const float4*)&As[kk][ty * 8 + 4];
            ulonglong2 b01 = *(const ulonglong2*)&Bs[kk][tx * 8];
            ulonglong2 b23 = *(const ulonglong2*)&Bs[kk][tx * 8 + 4];
            unsigned long long bp[4] = {b01.x, b01.y, b23.x, b23.y};
#pragma unroll
            for (int i = 0; i < 8; i++) {
                unsigned long long aa;
                PACK_F32X2(aa, a[i], a[i]);
#pragma unroll
                for (int j = 0; j < 4; j++)
                    FMA_F32X2(acc[i][j], aa, bp[j]);
            }
        }
        __syncthreads();
    }

    float bx[8];
#pragma unroll
    for (int q = 0; q < 8; q++) bx[q] = bxh[j0 + tx * 8 + q];

#pragma unroll
    for (int i = 0; i < 8; i++) {
        int l = l0 + ty * 8 + i;
        float* dst = g_xp + (size_t)l * (NB * HIDDEN) + n * HIDDEN + j0 + tx * 8;
        float r[8];
#pragma unroll
        for (int j = 0; j < 4; j++) {
            float lo, hi;
            UNPACK_F32X2(lo, hi, acc[i][j]);
            r[j * 2]     = lo + bx[j * 2];
            r[j * 2 + 1] = hi + bx[j * 2 + 1];
        }
        *(float4*)dst       = make_float4(r[0], r[1], r[2], r[3]);
        *(float4*)(dst + 4) = make_float4(r[4], r[5], r[6], r[7]);
    }
}

// ============================================================================
// Phase 2: persistent cluster RNN, 32 clusters x 4 CTAs (128 SMs), G=2 groups.
// Cluster g owns rows {2g, 2g+1}; group A = row 2g, group B = row 2g+1, each
// with own hbuf/red/mbar, R5-proven monolithic sync per group, interleaved so
// each group's cluster wait hides behind the other group's compute+push.
// W per thread = 128 ull: 80 ull in registers + 48 ull in smem (no spills).
// ============================================================================
#define CL       4
#define JSL      128
#define REG_IT   20                     // iters 0..19 from regs (80 ull)
#define SMEM_IT  12                     // iters 20..31 from smem (48 ull)

struct SmemR {
    ulonglong2 Wsm[SMEM_IT * 2 * 256];  // [plane][tid] 16B lanes: 98304 B
    float hbuf[2][2][HIDDEN];           // [group][buf][j]         8192 B
    float red[2][4][JSL];               // [group][kg][j]          4096 B
    float bh[JSL];                      //                         512 B
    unsigned long long mb[2];           // per-group mbarrier
};
#define SMEMR_BYTES ((int)sizeof(SmemR))

__device__ __forceinline__ uint32_t smem_u32(const void* p) {
    uint32_t a;
    asm("{ .reg .u64 t; cvta.to.shared.u64 t, %1; cvt.u32.u64 %0, t; }"
        : "=r"(a) : "l"(p));
    return a;
}
__device__ __forceinline__ uint32_t mapa_u32(uint32_t a, uint32_t rank) {
    uint32_t r;
    asm("mapa.shared::cluster.u32 %0, %1, %2;" : "=r"(r) : "r"(a), "r"(rank));
    return r;
}
__device__ __forceinline__ void stc_b32(uint32_t a, float v) {
    asm volatile("st.shared::cluster.b32 [%0], %1;"
                 :: "r"(a), "r"(__float_as_uint(v)) : "memory");
}
__device__ __forceinline__ void mbar_init(uint32_t a, uint32_t cnt) {
    asm volatile("mbarrier.init.shared.b64 [%0], %1;" :: "r"(a), "r"(cnt) : "memory");
}
__device__ __forceinline__ void mbar_arrive_remote(uint32_t a) {
    asm volatile("mbarrier.arrive.release.cluster.shared::cluster.b64 _, [%0];"
                 :: "r"(a) : "memory");
}
__device__ __forceinline__ void mbar_wait_parity(uint32_t a, uint32_t parity) {
    asm volatile(
        "{\n\t.reg .pred P;\n\t"
        "WL_%=:\n\t"
        "mbarrier.try_wait.parity.acquire.cluster.shared::cta.b64 P, [%0], %1, 0x989680;\n\t"
        "@!P bra WL_%=;\n\t}"
        :: "r"(a), "r"(parity) : "memory");
}
__device__ __forceinline__ void cluster_sync_() {
    asm volatile("barrier.cluster.arrive.aligned;" ::: "memory");
    asm volatile("barrier.cluster.wait.aligned;" ::: "memory");
}

// tanh = (e-1)/(e+1), e = 2^(2x*log2e); ~1e-6 abs err, branch-free.
__device__ __forceinline__ float fast_tanh(float x) {
    x = fminf(fmaxf(x, -15.0f), 15.0f);
    float e;
    asm("ex2.approx.f32 %0, %1;" : "=f"(e) : "f"(x * 2.8853900817779268f));
    float r;
    asm("rcp.approx.f32 %0, %1;" : "=f"(r) : "f"(e + 1.0f));
    return (e - 1.0f) * r;
}

extern __shared__ float smem_raw[];

__global__ void __cluster_dims__(CL, 1, 1) __launch_bounds__(256, 1)
rnn_kernel(const float* __restrict__ Whh, const float* __restrict__ bhh,
           float* __restrict__ out)
{
    SmemR* s = (SmemR*)smem_raw;
    const int tid  = threadIdx.x;
    const int rank = blockIdx.x;      // 0..3
    const int g    = blockIdx.y;      // 0..31
    const int j0   = rank * JSL;
    const int rowA = 2 * g;
    const int rowB = 2 * g + 1;

    const int kg = tid >> 6;          // 0..3 : k in [128kg, +128)
    const int jp = tid & 63;          // j-pair: jcol = j0 + jp*2

    // ---- W slice: 80 ull regs (iters 0..19) + 48 ull smem (iters 20..31) ----
    // Wr0[m] = (W[kb+2m][c0], W[kb+2m+1][c0]); Wr1 = same for c1. m = 2i, 2i+1.
    unsigned long long Wr0[2 * REG_IT], Wr1[2 * REG_IT];
    {
        const int kb   = kg * 128;
        const int jcol = j0 + jp * 2;
#pragma unroll
        for (int m = 0; m < 2 * REG_IT; m++) {
            int k = kb + m * 2;
            float2 w0 = *(const float2*)&Whh[(size_t)k * HIDDEN + jcol];
            float2 w1 = *(const float2*)&Whh[(size_t)(k + 1) * HIDDEN + jcol];
            PACK_F32X2(Wr0[m], w0.x, w1.x);
            PACK_F32X2(Wr1[m], w0.y, w1.y);
        }
        // smem planes: iter i (20..31): plane (i-20)*2 = col0 pair, +1 = col1
#pragma unroll
        for (int i = 0; i < SMEM_IT; i++) {
            unsigned long long p0a, p0b, p1a, p1b;
#pragma unroll
            for (int q = 0; q < 2; q++) {
                int m = 2 * (REG_IT + i) + q;
                int k = kb + m * 2;
                float2 w0 = *(const float2*)&Whh[(size_t)k * HIDDEN + jcol];
                float2 w1 = *(const float2*)&Whh[(size_t)(k + 1) * HIDDEN + jcol];
                unsigned long long u0, u1;
                PACK_F32X2(u0, w0.x, w1.x);
                PACK_F32X2(u1, w0.y, w1.y);
                if (q == 0) { p0a = u0; p1a = u1; }
                else        { p0b = u0; p1b = u1; }
            }
            s->Wsm[(i * 2 + 0) * 256 + tid] = make_ulonglong2(p0a, p0b);
            s->Wsm[(i * 2 + 1) * 256 + tid] = make_ulonglong2(p1a, p1b);
        }
    }

    // ---- smem init ----
    for (int idx = tid; idx < 2 * 2 * HIDDEN; idx += 256)
        ((float*)s->hbuf)[idx] = 0.f;
    if (tid < JSL) s->bh[tid] = bhh[j0 + tid];

    const uint32_t s_base = smem_u32(s);
    const uint32_t hbA    = smem_u32(&s->hbuf[0][0][0]) - s_base;
    const uint32_t hbB    = smem_u32(&s->hbuf[1][0][0]) - s_base;
    const uint32_t mbA    = smem_u32(&s->mb[0]) - s_base;
    const uint32_t mbB    = smem_u32(&s->mb[1]) - s_base;

    uint32_t peer_base[CL];
#pragma unroll
    for (int r = 0; r < CL; r++) peer_base[r] = mapa_u32(s_base, (uint32_t)r);

    if (tid == 0) {
        mbar_init(s_base + mbA, CL);
        mbar_init(s_base + mbB, CL);
        asm volatile("fence.mbarrier_init.release.cluster;" ::: "memory");
    }
    __syncthreads();
    cluster_sync_();   // W/h/bh/mbar visible cluster-wide

    // reduce/push role: tid<128 handles j = tid
    const int rj = tid & 127;
    const bool is_red = (tid < JSL);

    const size_t xstride = (size_t)NB * HIDDEN;
    const float* xpA = g_xp + (size_t)rowA * HIDDEN + j0 + rj;
    const float* xpB = g_xp + (size_t)rowB * HIDDEN + j0 + rj;

    float xA = __ldcs(xpA), xB = __ldcs(xpB);
    const float* xAn = xpA + xstride;
    const float* xBn = xpB + xstride;

    const ulonglong2* WsmT = &s->Wsm[tid];     // plane p at WsmT[p*256]

    for (int t = 0; t < LSTEPS; t++) {
        const int cur = t & 1;
        const int nxt = cur ^ 1;
        const uint32_t pw = (uint32_t)((t & 1) ^ 1);   // parity of step t-1
        float xAnx = (t + 1 < LSTEPS) ? __ldcs(xAn) : 0.f;
        float xBnx = (t + 1 < LSTEPS) ? __ldcs(xBn) : 0.f;

#pragma unroll 1
        for (int grp = 0; grp < 2; grp++) {
            const uint32_t mb_off = grp ? mbB : mbA;
            const uint32_t hb_off = grp ? hbB : hbA;

            if (t) mbar_wait_parity(s_base + mb_off, pw);

            // ---- inner product: 1 row x 2 cols x 128 k ----
            const ulonglong2* hv =
                (const ulonglong2*)&s->hbuf[grp][cur][kg * 128];
            unsigned long long a0 = 0ULL, a1 = 0ULL;
#pragma unroll
            for (int i = 0; i < REG_IT; i++) {
                ulonglong2 h = hv[i];
                FMA_F32X2(a0, Wr0[2 * i],     h.x);
                FMA_F32X2(a0, Wr0[2 * i + 1], h.y);
                FMA_F32X2(a1, Wr1[2 * i],     h.x);
                FMA_F32X2(a1, Wr1[2 * i + 1], h.y);
            }
#pragma unroll
            for (int i = 0; i < SMEM_IT; i++) {
                ulonglong2 h  = hv[REG_IT + i];
                ulonglong2 w0 = WsmT[(i * 2 + 0) * 256];
                ulonglong2 w1 = WsmT[(i * 2 + 1) * 256];
                FMA_F32X2(a0, w0.x, h.x);
                FMA_F32X2(a0, w0.y, h.y);
                FMA_F32X2(a1, w1.x, h.x);
                FMA_F32X2(a1, w1.y, h.y);
            }
            {
                float lo, hi, f0, f1;
                UNPACK_F32X2(lo, hi, a0); f0 = lo + hi;
                UNPACK_F32X2(lo, hi, a1); f1 = lo + hi;
                *(float2*)&s->red[grp][kg][jp * 2] = make_float2(f0, f1);
            }
            __syncthreads();

            // ---- reduce + tanh + push (tid < 128) ----
            if (is_red) {
                float xr = grp ? xB : xA;
                float sum = s->bh[rj] + xr
                          + s->red[grp][0][rj] + s->red[grp][1][rj]
                          + s->red[grp][2][rj] + s->red[grp][3][rj];
                float hn = fast_tanh(sum);

                if (t == LSTEPS - 1) {
                    int row = grp ? rowB : rowA;
                    out[row * HIDDEN + j0 + rj] = hn;
                } else {
                    const uint32_t off =
                        hb_off + (uint32_t)((nxt * HIDDEN + j0 + rj) * 4);
#pragma unroll
                    for (int r = 0; r < CL; r++)
                        stc_b32(peer_base[r] + off, hn);
                }
            }
            __syncthreads();
            if (t < LSTEPS - 1 && tid < CL)
                mbar_arrive_remote(peer_base[tid] + mb_off);
        }

        xA = xAnx; xB = xBnx;
        xAn += xstride; xBn += xstride;
    }
}

// ============================================================================
extern "C" void kernel_launch(void* const* d_in, const int* in_sizes, int n_in,
                              void* d_out, int out_size)
{
    const int*   X   = (const int*)d_in[0];
    const float* E   = (const float*)d_in[1];
    const float* Whh = (const float*)d_in[2];
    const float* bhh = (const float*)d_in[3];
    const float* Wxh = (const float*)d_in[4];
    const float* bxh = (const float*)d_in[5];
    float* out = (float*)d_out;

    cudaFuncSetAttribute(rnn_kernel,
                         cudaFuncAttributeMaxDynamicSharedMemorySize,
                         SMEMR_BYTES);

    proj_kernel<<<dim3(4, 1024), 256>>>(X, E, Wxh, bxh);
    rnn_kernel<<<dim3(CL, NB / 2), 256, SMEMR_BYTES>>>(Whh, bhh, out);
}